// round 1
// baseline (speedup 1.0000x reference)
#include <cuda_runtime.h>
#include <stdint.h>

#define BB 8
#define LL 4096
#define KK 576
#define DD 4096
#define IMG_TOK 32000
#define IGNORE (-100.0f)

// scratch: per-token code. >=0 : image feature row index (write)
//                          -1  : keep text embedding
//                          -2  : extra image placeholder -> zeros
__device__ int g_code[BB * LL];

// ---------------------------------------------------------------------------
// Kernel 1: per-row scans + all small outputs.  grid = B, block = 1024
// (each thread owns 4 consecutive tokens -> int4/float4 coalesced I/O)
// ---------------------------------------------------------------------------
__global__ __launch_bounds__(1024) void scan_kernel(
    const int* __restrict__ input_ids,
    const int* __restrict__ attention_mask,
    const int* __restrict__ labels,
    float* __restrict__ out_tail)   // points at out + B*L*D
{
    const int b = blockIdx.x;
    const int t = threadIdx.x;          // 0..1023
    const int lane = t & 31, wid = t >> 5;
    const int base = b * LL + t * 4;

    int4 id4 = *(const int4*)(input_ids + base);
    int4 am4 = *(const int4*)(attention_mask + base);
    int4 lb4 = *(const int4*)(labels + base);

    int im[4] = { id4.x == IMG_TOK, id4.y == IMG_TOK, id4.z == IMG_TOK, id4.w == IMG_TOK };
    int local = im[0] + im[1] + im[2] + im[3];

    __shared__ int warp_sums[32];

    // ---- scan #1: inclusive scan of per-thread image-token counts ----
    int v = local;
    #pragma unroll
    for (int o = 1; o < 32; o <<= 1) { int n = __shfl_up_sync(~0u, v, o); if (lane >= o) v += n; }
    if (lane == 31) warp_sums[wid] = v;
    __syncthreads();
    if (wid == 0) {
        int s = warp_sums[lane];
        #pragma unroll
        for (int o = 1; o < 32; o <<= 1) { int n = __shfl_up_sync(~0u, s, o); if (lane >= o) s += n; }
        warp_sums[lane] = s;
    }
    __syncthreads();
    // exclusive prefix (count of image tokens strictly before this thread's 4 tokens)
    int excl = (v - local) + (wid > 0 ? warp_sums[wid - 1] : 0);

    // per-element decisions
    int   code[4];
    int   fattn[4];
    float flab[4];
    float fmask[4];
    int am[4] = { am4.x, am4.y, am4.z, am4.w };
    int lb[4] = { lb4.x, lb4.y, lb4.z, lb4.w };

    int run = excl;
    #pragma unroll
    for (int i = 0; i < 4; i++) {
        if (im[i]) {
            int rank = run;                 // inclusive cumsum - 1 == exclusive count
            run++;
            if (rank < KK) {                // write position
                code[i]  = rank;
                fattn[i] = 1;
                fmask[i] = 1.0f;            // id stays 32000 -> mask true
            } else {                        // extra placeholder
                code[i]  = -2;
                fattn[i] = 0;
                fmask[i] = 0.0f;            // id -> PAD(0)
            }
            flab[i] = IGNORE;
        } else {
            code[i]  = -1;
            fattn[i] = am[i];
            flab[i]  = (float)lb[i];
            fmask[i] = 0.0f;                // non-image id can't be 32000 here
        }
    }

    __syncthreads();   // reuse warp_sums

    // ---- scan #2: inclusive scan of final attention mask -> position_ids ----
    int local2 = fattn[0] + fattn[1] + fattn[2] + fattn[3];
    int v2 = local2;
    #pragma unroll
    for (int o = 1; o < 32; o <<= 1) { int n = __shfl_up_sync(~0u, v2, o); if (lane >= o) v2 += n; }
    if (lane == 31) warp_sums[wid] = v2;
    __syncthreads();
    if (wid == 0) {
        int s = warp_sums[lane];
        #pragma unroll
        for (int o = 1; o < 32; o <<= 1) { int n = __shfl_up_sync(~0u, s, o); if (lane >= o) s += n; }
        warp_sums[lane] = s;
    }
    __syncthreads();
    int excl2 = (v2 - local2) + (wid > 0 ? warp_sums[wid - 1] : 0);

    float fpos[4];
    int csum = excl2;
    #pragma unroll
    for (int i = 0; i < 4; i++) {
        csum += fattn[i];
        int p = csum - 1;
        fpos[i] = (float)(p < 0 ? 0 : p);
    }

    // ---- stores ----
    *(int4*)(g_code + base) = make_int4(code[0], code[1], code[2], code[3]);

    const int NTOK = BB * LL;
    float4 fa = make_float4((float)fattn[0], (float)fattn[1], (float)fattn[2], (float)fattn[3]);
    *(float4*)(out_tail + 0 * NTOK + base) = fa;                                           // attn
    *(float4*)(out_tail + 1 * NTOK + base) = make_float4(flab[0], flab[1], flab[2], flab[3]); // labels
    *(float4*)(out_tail + 2 * NTOK + base) = make_float4(fpos[0], fpos[1], fpos[2], fpos[3]); // position_ids
    *(float4*)(out_tail + 3 * NTOK + base) = make_float4(fmask[0], fmask[1], fmask[2], fmask[3]); // img mask
}

// ---------------------------------------------------------------------------
// Kernel 2: embedding assembly.  One block per token row, 256 threads,
// each moves 4 float4 (64 B) -> 16 KB per row, fully coalesced streams.
// ---------------------------------------------------------------------------
__global__ __launch_bounds__(256) void copy_kernel(
    const float4* __restrict__ feat,   // (B,K,D)
    const float4* __restrict__ emb,    // (B,L,D)
    float4* __restrict__ out)          // (B,L,D)
{
    const int row  = blockIdx.x;            // 0 .. B*L-1
    const int code = g_code[row];
    const int tid  = threadIdx.x;
    const int D4   = DD / 4;                // 1024 float4 per row

    float4* dst = out + (size_t)row * D4;

    if (code == -2) {                       // extra placeholder -> zeros
        float4 z = make_float4(0.f, 0.f, 0.f, 0.f);
        #pragma unroll
        for (int i = 0; i < 4; i++) dst[i * 256 + tid] = z;
        return;
    }

    const float4* src;
    if (code >= 0) {
        int b = row >> 12;                  // row / L
        src = feat + ((size_t)b * KK + code) * D4;
    } else {
        src = emb + (size_t)row * D4;
    }
    #pragma unroll
    for (int i = 0; i < 4; i++) dst[i * 256 + tid] = src[i * 256 + tid];
}

// ---------------------------------------------------------------------------
extern "C" void kernel_launch(void* const* d_in, const int* in_sizes, int n_in,
                              void* d_out, int out_size)
{
    const float* image_features = (const float*)d_in[0];   // (B,K,D) f32
    const float* inputs_embeds  = (const float*)d_in[1];   // (B,L,D) f32
    const int*   input_ids      = (const int*)d_in[2];     // (B,L) i32
    const int*   attention_mask = (const int*)d_in[3];     // (B,L) i32
    const int*   labels         = (const int*)d_in[4];     // (B,L) i32

    float* out = (float*)d_out;
    float* out_tail = out + (size_t)BB * LL * DD;

    scan_kernel<<<BB, 1024>>>(input_ids, attention_mask, labels, out_tail);
    copy_kernel<<<BB * LL, 256>>>((const float4*)image_features,
                                  (const float4*)inputs_embeds,
                                  (float4*)out);
}

// round 2
// speedup vs baseline: 1.0050x; 1.0050x over previous
#include <cuda_runtime.h>
#include <stdint.h>

#define BB 8
#define LL 4096
#define KK 576
#define DD 4096
#define IMG_TOK 32000
#define IGNORE (-100.0f)

// scratch: per-token code. >=0 : image feature row index (write)
//                          -1  : keep text embedding
//                          -2  : extra image placeholder -> zeros
__device__ int g_code[BB * LL];

// ---------------------------------------------------------------------------
// Kernel 1: per-row scans + all small outputs.  grid = B, block = 1024
// (each thread owns 4 consecutive tokens -> int4/float4 coalesced I/O)
// Triggers dependent (copy) launch as soon as g_code is globally visible.
// ---------------------------------------------------------------------------
__global__ __launch_bounds__(1024) void scan_kernel(
    const int* __restrict__ input_ids,
    const int* __restrict__ attention_mask,
    const int* __restrict__ labels,
    float* __restrict__ out_tail)   // points at out + B*L*D
{
    const int b = blockIdx.x;
    const int t = threadIdx.x;          // 0..1023
    const int lane = t & 31, wid = t >> 5;
    const int base = b * LL + t * 4;

    int4 id4 = *(const int4*)(input_ids + base);
    int4 am4 = *(const int4*)(attention_mask + base);
    int4 lb4 = *(const int4*)(labels + base);

    int im[4] = { id4.x == IMG_TOK, id4.y == IMG_TOK, id4.z == IMG_TOK, id4.w == IMG_TOK };
    int local = im[0] + im[1] + im[2] + im[3];

    __shared__ int warp_sums[32];

    // ---- scan #1: inclusive scan of per-thread image-token counts ----
    int v = local;
    #pragma unroll
    for (int o = 1; o < 32; o <<= 1) { int n = __shfl_up_sync(~0u, v, o); if (lane >= o) v += n; }
    if (lane == 31) warp_sums[wid] = v;
    __syncthreads();
    if (wid == 0) {
        int s = warp_sums[lane];
        #pragma unroll
        for (int o = 1; o < 32; o <<= 1) { int n = __shfl_up_sync(~0u, s, o); if (lane >= o) s += n; }
        warp_sums[lane] = s;
    }
    __syncthreads();
    // exclusive prefix (count of image tokens strictly before this thread's 4 tokens)
    int excl = (v - local) + (wid > 0 ? warp_sums[wid - 1] : 0);

    // per-element decisions
    int   code[4];
    int   fattn[4];
    float flab[4];
    float fmask[4];
    int am[4] = { am4.x, am4.y, am4.z, am4.w };
    int lb[4] = { lb4.x, lb4.y, lb4.z, lb4.w };

    int run = excl;
    #pragma unroll
    for (int i = 0; i < 4; i++) {
        if (im[i]) {
            int rank = run;                 // inclusive cumsum - 1 == exclusive count
            run++;
            if (rank < KK) {                // write position
                code[i]  = rank;
                fattn[i] = 1;
                fmask[i] = 1.0f;            // id stays 32000 -> mask true
            } else {                        // extra placeholder
                code[i]  = -2;
                fattn[i] = 0;
                fmask[i] = 0.0f;            // id -> PAD(0)
            }
            flab[i] = IGNORE;
        } else {
            code[i]  = -1;
            fattn[i] = am[i];
            flab[i]  = (float)lb[i];
            fmask[i] = 0.0f;                // non-image id can't be 32000 here
        }
    }

    // ---- publish g_code ASAP, then release the dependent copy kernel ----
    *(int4*)(g_code + base) = make_int4(code[0], code[1], code[2], code[3]);
    __threadfence();                       // make g_code visible device-wide
    asm volatile("griddepcontrol.launch_dependents;" ::: "memory");

    __syncthreads();   // reuse warp_sums

    // ---- scan #2: inclusive scan of final attention mask -> position_ids ----
    int local2 = fattn[0] + fattn[1] + fattn[2] + fattn[3];
    int v2 = local2;
    #pragma unroll
    for (int o = 1; o < 32; o <<= 1) { int n = __shfl_up_sync(~0u, v2, o); if (lane >= o) v2 += n; }
    if (lane == 31) warp_sums[wid] = v2;
    __syncthreads();
    if (wid == 0) {
        int s = warp_sums[lane];
        #pragma unroll
        for (int o = 1; o < 32; o <<= 1) { int n = __shfl_up_sync(~0u, s, o); if (lane >= o) s += n; }
        warp_sums[lane] = s;
    }
    __syncthreads();
    int excl2 = (v2 - local2) + (wid > 0 ? warp_sums[wid - 1] : 0);

    float fpos[4];
    int csum = excl2;
    #pragma unroll
    for (int i = 0; i < 4; i++) {
        csum += fattn[i];
        int p = csum - 1;
        fpos[i] = (float)(p < 0 ? 0 : p);
    }

    // ---- small-output stores (overlap with copy kernel's ramp-up) ----
    const int NTOK = BB * LL;
    float4 fa = make_float4((float)fattn[0], (float)fattn[1], (float)fattn[2], (float)fattn[3]);
    *(float4*)(out_tail + 0 * NTOK + base) = fa;                                              // attn
    *(float4*)(out_tail + 1 * NTOK + base) = make_float4(flab[0], flab[1], flab[2], flab[3]); // labels
    *(float4*)(out_tail + 2 * NTOK + base) = make_float4(fpos[0], fpos[1], fpos[2], fpos[3]); // position_ids
    *(float4*)(out_tail + 3 * NTOK + base) = make_float4(fmask[0], fmask[1], fmask[2], fmask[3]); // img mask
}

// ---------------------------------------------------------------------------
// Kernel 2: embedding assembly.  Two token rows per block, 512 threads.
// Each half-block (256 threads) streams one 16 KB row as 4 float4 per thread.
// Launched with PDL; waits on scan's trigger before reading g_code.
// ---------------------------------------------------------------------------
__global__ __launch_bounds__(512) void copy_kernel(
    const float4* __restrict__ feat,   // (B,K,D)
    const float4* __restrict__ emb,    // (B,L,D)
    float4* __restrict__ out)          // (B,L,D)
{
    asm volatile("griddepcontrol.wait;" ::: "memory");

    const int half = threadIdx.x >> 8;            // 0 or 1: which row of the pair
    const int tid  = threadIdx.x & 255;           // 0..255 within the row
    const int row  = blockIdx.x * 2 + half;       // 0 .. B*L-1
    const int code = __ldg(g_code + row);
    const int D4   = DD / 4;                      // 1024 float4 per row

    float4* dst = out + (size_t)row * D4;

    if (code == -2) {                             // extra placeholder -> zeros
        float4 z = make_float4(0.f, 0.f, 0.f, 0.f);
        #pragma unroll
        for (int i = 0; i < 4; i++) dst[i * 256 + tid] = z;
        return;
    }

    const float4* src;
    if (code >= 0) {
        int b = row >> 12;                        // row / L
        src = feat + ((size_t)b * KK + code) * D4;
    } else {
        src = emb + (size_t)row * D4;
    }

    float4 r0 = src[0 * 256 + tid];
    float4 r1 = src[1 * 256 + tid];
    float4 r2 = src[2 * 256 + tid];
    float4 r3 = src[3 * 256 + tid];
    dst[0 * 256 + tid] = r0;
    dst[1 * 256 + tid] = r1;
    dst[2 * 256 + tid] = r2;
    dst[3 * 256 + tid] = r3;
}

// ---------------------------------------------------------------------------
extern "C" void kernel_launch(void* const* d_in, const int* in_sizes, int n_in,
                              void* d_out, int out_size)
{
    const float* image_features = (const float*)d_in[0];   // (B,K,D) f32
    const float* inputs_embeds  = (const float*)d_in[1];   // (B,L,D) f32
    const int*   input_ids      = (const int*)d_in[2];     // (B,L) i32
    const int*   attention_mask = (const int*)d_in[3];     // (B,L) i32
    const int*   labels         = (const int*)d_in[4];     // (B,L) i32

    float* out = (float*)d_out;
    float* out_tail = out + (size_t)BB * LL * DD;

    scan_kernel<<<BB, 1024>>>(input_ids, attention_mask, labels, out_tail);

    // PDL launch: copy may begin while scan is still running; the
    // griddepcontrol.wait inside copy gates on scan's launch_dependents.
    cudaLaunchConfig_t cfg = {};
    cfg.gridDim  = dim3(BB * LL / 2);
    cfg.blockDim = dim3(512);
    cfg.dynamicSmemBytes = 0;
    cfg.stream = 0;
    cudaLaunchAttribute attrs[1];
    attrs[0].id = cudaLaunchAttributeProgrammaticStreamSerialization;
    attrs[0].val.programmaticStreamSerializationAllowed = 1;
    cfg.attrs = attrs;
    cfg.numAttrs = 1;
    cudaLaunchKernelEx(&cfg, copy_kernel,
                       (const float4*)image_features,
                       (const float4*)inputs_embeds,
                       (float4*)out);
}

// round 3
// speedup vs baseline: 1.0122x; 1.0072x over previous
#include <cuda_runtime.h>
#include <stdint.h>

#define BB 8
#define LL 4096
#define KK 576
#define DD 4096
#define IMG_TOK 32000
#define IGNORE (-100.0f)
#define NSCAN BB                 // one scan block per batch row
#define ROWS_PER_BLK 4           // copy blocks handle 4 token rows each
#define NCOPY (BB * LL / ROWS_PER_BLK)   // 8192

// scratch: per-token code. >=0 : image feature row index (write)
//                          -1  : keep text embedding
//                          -2  : extra image placeholder -> zeros
__device__ int g_code[BB * LL];
__device__ volatile int g_row_ready[BB];   // per-batch-row flag (reset each run)
__device__ unsigned int g_done;            // completion counter (reset each run)

// ---------------------------------------------------------------------------
// Fused kernel. blocks [0,8): per-row scan + small outputs (publish g_code
// + flag ASAP).  blocks [8, 8+8192): stream 4 embedding rows each, gated on
// the row flag.  One grid, one graph node.
// ---------------------------------------------------------------------------
__global__ __launch_bounds__(1024) void fused_kernel(
    const int*    __restrict__ input_ids,
    const int*    __restrict__ attention_mask,
    const int*    __restrict__ labels,
    const float4* __restrict__ feat,       // (B,K,D)
    const float4* __restrict__ emb,        // (B,L,D)
    float4*       __restrict__ out,        // (B,L,D)
    float*        __restrict__ out_tail)   // out + B*L*D
{
    const int bid = blockIdx.x;

    if (bid < NSCAN) {
        // ================= SCAN PATH =================
        const int b = bid;
        const int t = threadIdx.x;          // 0..1023, 4 tokens each
        const int lane = t & 31, wid = t >> 5;
        const int base = b * LL + t * 4;

        int4 id4 = *(const int4*)(input_ids + base);

        int im[4] = { id4.x == IMG_TOK, id4.y == IMG_TOK,
                      id4.z == IMG_TOK, id4.w == IMG_TOK };
        int local = im[0] + im[1] + im[2] + im[3];

        __shared__ int warp_sums[32];

        // ---- scan #1: image-token ranks ----
        int v = local;
        #pragma unroll
        for (int o = 1; o < 32; o <<= 1) { int n = __shfl_up_sync(~0u, v, o); if (lane >= o) v += n; }
        if (lane == 31) warp_sums[wid] = v;
        __syncthreads();
        if (wid == 0) {
            int s = warp_sums[lane];
            #pragma unroll
            for (int o = 1; o < 32; o <<= 1) { int n = __shfl_up_sync(~0u, s, o); if (lane >= o) s += n; }
            warp_sums[lane] = s;
        }
        __syncthreads();
        int excl = (v - local) + (wid > 0 ? warp_sums[wid - 1] : 0);

        int code[4], fattn[4];
        float fmask[4];
        int run = excl;
        int4 am4 = *(const int4*)(attention_mask + base);
        int am[4] = { am4.x, am4.y, am4.z, am4.w };
        #pragma unroll
        for (int i = 0; i < 4; i++) {
            if (im[i]) {
                int rank = run++;
                if (rank < KK) { code[i] = rank; fattn[i] = 1; fmask[i] = 1.0f; }
                else           { code[i] = -2;  fattn[i] = 0; fmask[i] = 0.0f; }
            } else {
                code[i] = -1; fattn[i] = am[i]; fmask[i] = 0.0f;
            }
        }

        // ---- publish g_code, then raise the row flag ----
        *(int4*)(g_code + base) = make_int4(code[0], code[1], code[2], code[3]);
        __threadfence();
        __syncthreads();
        if (t == 0) g_row_ready[b] = 1;

        // ---- remaining small outputs (overlap with copy traffic) ----
        int4 lb4 = *(const int4*)(labels + base);
        int lb[4] = { lb4.x, lb4.y, lb4.z, lb4.w };
        float flab[4];
        #pragma unroll
        for (int i = 0; i < 4; i++)
            flab[i] = im[i] ? IGNORE : (float)lb[i];

        __syncthreads();   // reuse warp_sums
        // ---- scan #2: final attention mask -> position_ids ----
        int local2 = fattn[0] + fattn[1] + fattn[2] + fattn[3];
        int v2 = local2;
        #pragma unroll
        for (int o = 1; o < 32; o <<= 1) { int n = __shfl_up_sync(~0u, v2, o); if (lane >= o) v2 += n; }
        if (lane == 31) warp_sums[wid] = v2;
        __syncthreads();
        if (wid == 0) {
            int s = warp_sums[lane];
            #pragma unroll
            for (int o = 1; o < 32; o <<= 1) { int n = __shfl_up_sync(~0u, s, o); if (lane >= o) s += n; }
            warp_sums[lane] = s;
        }
        __syncthreads();
        int excl2 = (v2 - local2) + (wid > 0 ? warp_sums[wid - 1] : 0);

        float fpos[4];
        int csum = excl2;
        #pragma unroll
        for (int i = 0; i < 4; i++) {
            csum += fattn[i];
            int p = csum - 1;
            fpos[i] = (float)(p < 0 ? 0 : p);
        }

        const int NTOK = BB * LL;
        *(float4*)(out_tail + 0 * NTOK + base) =
            make_float4((float)fattn[0], (float)fattn[1], (float)fattn[2], (float)fattn[3]);
        *(float4*)(out_tail + 1 * NTOK + base) = make_float4(flab[0], flab[1], flab[2], flab[3]);
        *(float4*)(out_tail + 2 * NTOK + base) = make_float4(fpos[0], fpos[1], fpos[2], fpos[3]);
        *(float4*)(out_tail + 3 * NTOK + base) = make_float4(fmask[0], fmask[1], fmask[2], fmask[3]);
    } else {
        // ================= COPY PATH =================
        const int base_row = (bid - NSCAN) * ROWS_PER_BLK;   // 4 rows, same batch b
        const int b = base_row >> 12;

        if (threadIdx.x == 0) {
            while (g_row_ready[b] == 0) __nanosleep(64);
            __threadfence();            // acquire: order g_code reads after flag
        }
        __syncthreads();

        const int quarter = threadIdx.x >> 8;       // 0..3: which row
        const int tid     = threadIdx.x & 255;      // 0..255 within the row
        const int row     = base_row + quarter;
        const int code    = g_code[row];
        const int D4      = DD / 4;                 // 1024 float4 per row

        float4* dst = out + (size_t)row * D4;

        if (code == -2) {                           // extra placeholder -> zeros
            float4 z = make_float4(0.f, 0.f, 0.f, 0.f);
            #pragma unroll
            for (int i = 0; i < 4; i++) __stcs(dst + i * 256 + tid, z);
        } else {
            const float4* src = (code >= 0)
                ? feat + ((size_t)b * KK + code) * D4
                : emb  + (size_t)row * D4;

            float4 r0 = __ldcs(src + 0 * 256 + tid);
            float4 r1 = __ldcs(src + 1 * 256 + tid);
            float4 r2 = __ldcs(src + 2 * 256 + tid);
            float4 r3 = __ldcs(src + 3 * 256 + tid);
            __stcs(dst + 0 * 256 + tid, r0);
            __stcs(dst + 1 * 256 + tid, r1);
            __stcs(dst + 2 * 256 + tid, r2);
            __stcs(dst + 3 * 256 + tid, r3);
        }
    }

    // ---- epilogue: last block resets inter-block state for next replay ----
    __syncthreads();
    if (threadIdx.x == 0) {
        __threadfence();
        unsigned t = atomicAdd(&g_done, 1);
        if (t == gridDim.x - 1) {
            #pragma unroll
            for (int i = 0; i < NSCAN; i++) g_row_ready[i] = 0;
            __threadfence();
            g_done = 0;
        }
    }
}

// ---------------------------------------------------------------------------
extern "C" void kernel_launch(void* const* d_in, const int* in_sizes, int n_in,
                              void* d_out, int out_size)
{
    const float* image_features = (const float*)d_in[0];   // (B,K,D) f32
    const float* inputs_embeds  = (const float*)d_in[1];   // (B,L,D) f32
    const int*   input_ids      = (const int*)d_in[2];     // (B,L) i32
    const int*   attention_mask = (const int*)d_in[3];     // (B,L) i32
    const int*   labels         = (const int*)d_in[4];     // (B,L) i32

    float* out = (float*)d_out;
    float* out_tail = out + (size_t)BB * LL * DD;

    fused_kernel<<<NSCAN + NCOPY, 1024>>>(
        input_ids, attention_mask, labels,
        (const float4*)image_features,
        (const float4*)inputs_embeds,
        (float4*)out, out_tail);
}